// round 3
// baseline (speedup 1.0000x reference)
#include <cuda_runtime.h>
#include <cuda_bf16.h>
#include <cstdint>

#define BMAX 8192
#define DMAX 256

#define TILE 128
#define KC   64
#define LDSA 72   // smem row stride in bf16 elems; 144B pitch -> conflict-free LDSM

// Scratch (allocation-free rule: __device__ globals)
__device__ __align__(16) __nv_bfloat16 g_xb[BMAX * DMAX];
__device__ float  g_sqn[BMAX];
__device__ float  g_rs[BMAX];
__device__ int    g_lab[BMAX];
__device__ double g_acc;
__device__ int    g_done;   // zero-init; reset by last CTA each replay

// prep: blocks [0,B) convert row to bf16 + row sums; block B detects label
// dtype (int64 -> all odd int32 words are zero high-halves), normalizes labels,
// and zeroes the accumulator.
__global__ void prep_kernel(const float* __restrict__ x,
                            const int* __restrict__ lab32, int B, int D) {
    int blk = blockIdx.x;
    int t = threadIdx.x;
    if (blk == B) {
        // label dtype detection + normalization + acc zero
        __shared__ int s_any;
        if (t == 0) { s_any = 0; g_acc = 0.0; }
        __syncthreads();
        int any = 0;
        for (int idx = 1 + 2 * t; idx < 2 * B; idx += 2 * blockDim.x)
            any |= lab32[idx];        // safe: if int32, buffer has B words; cap below
        // NOTE: if labels are int32 the buffer is only B words; restrict scan:
        // redo with safe bound (B words). Odd indices < B only.
        (void)any;
        any = 0;
        for (int idx = 1 + 2 * t; idx < B; idx += 2 * blockDim.x)
            any |= lab32[idx];
        if (any) atomicOr(&s_any, 1);
        __syncthreads();
        int is32 = (s_any != 0);
        for (int r = t; r < B; r += blockDim.x)
            g_lab[r] = is32 ? lab32[r] : lab32[2 * r];
        return;
    }
    int row = blk;
    float s = 0.f, ss = 0.f;
    for (int c = t; c < D; c += blockDim.x) {
        float v = x[(size_t)row * D + c];
        g_xb[(size_t)row * D + c] = __float2bfloat16(v);
        s += v;
        ss += v * v;
    }
    #pragma unroll
    for (int o = 16; o > 0; o >>= 1) {
        s  += __shfl_down_sync(0xffffffffu, s,  o);
        ss += __shfl_down_sync(0xffffffffu, ss, o);
    }
    __shared__ float sh_s[8], sh_ss[8];
    int w = t >> 5, l = t & 31;
    if (l == 0) { sh_s[w] = s; sh_ss[w] = ss; }
    __syncthreads();
    if (t == 0) {
        float S = 0.f, SS = 0.f;
        int nw = blockDim.x >> 5;
        for (int i = 0; i < nw; i++) { S += sh_s[i]; SS += sh_ss[i]; }
        g_rs[row]  = S;
        g_sqn[row] = SS;
    }
}

__device__ __forceinline__ uint32_t smem_u32(const void* p) {
    return (uint32_t)__cvta_generic_to_shared(p);
}

// Upper-triangle tiled pairwise kernel with fused finalize.
// CTA = 128x128 tile, 8 warps 2x4, warp tile 64x32, mma m16n8k16 bf16,
// ldmatrix fragment loads, cp.async staging, 2 CTAs/SM.
__global__ __launch_bounds__(256, 2) void pair_kernel(float* __restrict__ out,
                                                      int B, int D, int NT,
                                                      double inv) {
    __shared__ __nv_bfloat16 sA[TILE * LDSA];
    __shared__ __nv_bfloat16 sB[TILE * LDSA];
    __shared__ float red[8];

    int p = blockIdx.x;
    int ti = 0;
    while (p >= NT - ti) { p -= NT - ti; ti++; }
    int tj = ti + p;

    const int tid  = threadIdx.x;
    const int warp = tid >> 5;
    const int lane = tid & 31;
    const int grp  = lane >> 2;
    const int tg   = lane & 3;
    const int wm   = warp >> 2;   // 0..1
    const int wn   = warp & 3;    // 0..3

    float acc[4][4][4];
    #pragma unroll
    for (int a = 0; a < 4; a++)
        #pragma unroll
        for (int b = 0; b < 4; b++)
            #pragma unroll
            for (int c = 0; c < 4; c++) acc[a][b][c] = 0.f;

    const int r0 = ti * TILE;
    const int c0 = tj * TILE;

    // ldmatrix base addresses (byte offsets into smem)
    const int rowA = wm * 64 + (lane & 15);
    const int aSel = (lane >> 4) * 8;
    const uint32_t aBase = smem_u32(sA) + (uint32_t)(rowA * LDSA + aSel) * 2u;
    const int colB = wn * 32 + ((lane >> 4) << 3) + (lane & 7);
    const int bSel = ((lane >> 3) & 1) * 8;
    const uint32_t bBase = smem_u32(sB) + (uint32_t)(colB * LDSA + bSel) * 2u;

    // staging addresses
    const int sRow = tid >> 3;          // 0..31 (row step 32 per it)
    const int sC8  = tid & 7;

    for (int kc = 0; kc < D; kc += KC) {
        if (kc) __syncthreads();
        #pragma unroll
        for (int it = 0; it < 4; it++) {
            int row = sRow + 32 * it;
            uint32_t sa = smem_u32(sA) + (uint32_t)(row * LDSA + sC8 * 8) * 2u;
            uint32_t sb = smem_u32(sB) + (uint32_t)(row * LDSA + sC8 * 8) * 2u;
            const void* ga = &g_xb[(size_t)(r0 + row) * D + kc + sC8 * 8];
            const void* gb = &g_xb[(size_t)(c0 + row) * D + kc + sC8 * 8];
            asm volatile("cp.async.ca.shared.global [%0], [%1], 16;\n" :: "r"(sa), "l"(ga));
            asm volatile("cp.async.ca.shared.global [%0], [%1], 16;\n" :: "r"(sb), "l"(gb));
        }
        asm volatile("cp.async.commit_group;\n");
        asm volatile("cp.async.wait_group 0;\n");
        __syncthreads();

        #pragma unroll
        for (int ks = 0; ks < KC / 16; ks++) {
            uint32_t af[4][4];
            #pragma unroll
            for (int mt = 0; mt < 4; mt++) {
                uint32_t addr = aBase + (uint32_t)(mt * 16 * LDSA) * 2u + (uint32_t)ks * 32u;
                asm volatile("ldmatrix.sync.aligned.m8n8.x4.shared.b16 {%0,%1,%2,%3}, [%4];\n"
                             : "=r"(af[mt][0]), "=r"(af[mt][1]), "=r"(af[mt][2]), "=r"(af[mt][3])
                             : "r"(addr));
            }
            uint32_t bf[4][2];
            #pragma unroll
            for (int np = 0; np < 2; np++) {
                uint32_t addr = bBase + (uint32_t)(np * 16 * LDSA) * 2u + (uint32_t)ks * 32u;
                asm volatile("ldmatrix.sync.aligned.m8n8.x4.shared.b16 {%0,%1,%2,%3}, [%4];\n"
                             : "=r"(bf[2 * np][0]), "=r"(bf[2 * np][1]),
                               "=r"(bf[2 * np + 1][0]), "=r"(bf[2 * np + 1][1])
                             : "r"(addr));
            }
            #pragma unroll
            for (int mt = 0; mt < 4; mt++)
                #pragma unroll
                for (int nt = 0; nt < 4; nt++) {
                    float* d = acc[mt][nt];
                    asm volatile(
                        "mma.sync.aligned.m16n8k16.row.col.f32.bf16.bf16.f32 "
                        "{%0,%1,%2,%3}, {%4,%5,%6,%7}, {%8,%9}, {%0,%1,%2,%3};\n"
                        : "+f"(d[0]), "+f"(d[1]), "+f"(d[2]), "+f"(d[3])
                        : "r"(af[mt][0]), "r"(af[mt][1]), "r"(af[mt][2]), "r"(af[mt][3]),
                          "r"(bf[nt][0]), "r"(bf[nt][1]));
                }
        }
    }

    // Epilogue
    int iRow[8]; float sqI[8], rsI[8]; int lbI[8];
    #pragma unroll
    for (int mt = 0; mt < 4; mt++) {
        int i0 = r0 + wm * 64 + mt * 16 + grp;
        iRow[mt * 2]     = i0;
        iRow[mt * 2 + 1] = i0 + 8;
    }
    #pragma unroll
    for (int u = 0; u < 8; u++) {
        sqI[u] = g_sqn[iRow[u]];
        rsI[u] = g_rs[iRow[u]];
        lbI[u] = g_lab[iRow[u]];
    }
    int jCol[8]; float sqJ[8], rsJ[8]; int lbJ[8];
    #pragma unroll
    for (int nt = 0; nt < 4; nt++) {
        int j0 = c0 + wn * 32 + nt * 8 + tg * 2;
        jCol[nt * 2]     = j0;
        jCol[nt * 2 + 1] = j0 + 1;
    }
    #pragma unroll
    for (int u = 0; u < 8; u++) {
        sqJ[u] = g_sqn[jCol[u]];
        rsJ[u] = g_rs[jCol[u]];
        lbJ[u] = g_lab[jCol[u]];
    }

    const float D_EPS2 = (float)D * 1e-6f * 1e-6f;
    float tsum = 0.f;
    #pragma unroll
    for (int mt = 0; mt < 4; mt++)
        #pragma unroll
        for (int nt = 0; nt < 4; nt++)
            #pragma unroll
            for (int h = 0; h < 4; h++) {
                int ui = mt * 2 + (h >> 1);
                int uj = nt * 2 + (h & 1);
                int i = iRow[ui], j = jCol[uj];
                if (j > i) {
                    float gv = acc[mt][nt][h];
                    float sq = sqI[ui] + sqJ[uj] - 2.0f * gv
                             + 2e-6f * (rsI[ui] - rsJ[uj]) + D_EPS2;
                    float val;
                    if (lbI[ui] == lbJ[uj]) {
                        val = fmaxf(sq, 1e-12f);
                    } else {
                        float dd = sqrtf(fmaxf(sq, 1e-12f));
                        float tt = fmaxf(1.0f - dd, 0.0f);
                        val = tt * tt;
                    }
                    tsum += val;
                }
            }

    #pragma unroll
    for (int o = 16; o > 0; o >>= 1)
        tsum += __shfl_down_sync(0xffffffffu, tsum, o);
    if (lane == 0) red[warp] = tsum;
    __syncthreads();
    if (tid == 0) {
        float s = 0.f;
        #pragma unroll
        for (int i = 0; i < 8; i++) s += red[i];
        atomicAdd(&g_acc, (double)s);
        __threadfence();
        int t = atomicAdd(&g_done, 1);
        if (t == (int)gridDim.x - 1) {
            g_done = 0;                       // reset for next replay
            out[0] = (float)(g_acc * inv);    // fused finalize
        }
    }
}

extern "C" void kernel_launch(void* const* d_in, const int* in_sizes, int n_in,
                              void* d_out, int out_size) {
    const float* x     = (const float*)d_in[0];
    const int*   lab32 = (const int*)d_in[1];
    int B = in_sizes[1];
    int D = in_sizes[0] / B;
    int NT = B / TILE;
    int tiles = NT * (NT + 1) / 2;
    double cnt = (double)B * (B - 1) / 2.0;
    double inv = 1.0 / (cnt + 1e-6);

    prep_kernel<<<B + 1, 256>>>(x, lab32, B, D);
    pair_kernel<<<tiles, 256>>>((float*)d_out, B, D, NT, inv);
}

// round 4
// speedup vs baseline: 1.9711x; 1.9711x over previous
#include <cuda_runtime.h>
#include <cuda_bf16.h>
#include <cstdint>

#define BMAX 8192
#define DMAX 256

#define TILE 128
#define KC   64
#define LDSA 72   // smem row stride (bf16 elems); 144B pitch, conflict-free LDSM

#define STAGE_BYTES (2u * TILE * LDSA * 2u)     // A+B tiles per stage
#define SMEM_DYN    (2u * STAGE_BYTES)          // 2 stages = 73728 B

// Scratch (allocation-free rule: __device__ globals)
__device__ __align__(16) __nv_bfloat16 g_xb[BMAX * DMAX];
__device__ float  g_u[BMAX];     // sqn + 2eps*rs + D*eps^2
__device__ float  g_v[BMAX];     // sqn - 2eps*rs
__device__ int    g_lab[BMAX];
__device__ double g_acc;
__device__ int    g_done;        // zero-init; reset by finalizing CTA each replay

// prep: blocks [0,B) convert row to bf16 + row stats; block B detects label
// dtype (int64 -> all odd int32 words zero), normalizes labels, zeroes acc.
__global__ void prep_kernel(const float* __restrict__ x,
                            const int* __restrict__ lab32, int B, int D) {
    int blk = blockIdx.x;
    int t = threadIdx.x;
    if (blk == B) {
        __shared__ int s_any;
        if (t == 0) { s_any = 0; g_acc = 0.0; }
        __syncthreads();
        int any = 0;
        for (int idx = 1 + 2 * t; idx < B; idx += 2 * blockDim.x)
            any |= lab32[idx];
        if (any) atomicOr(&s_any, 1);
        __syncthreads();
        int is32 = (s_any != 0);
        for (int r = t; r < B; r += blockDim.x)
            g_lab[r] = is32 ? lab32[r] : lab32[2 * r];
        return;
    }
    int row = blk;
    float s = 0.f, ss = 0.f;
    for (int c = t; c < D; c += blockDim.x) {
        float v = x[(size_t)row * D + c];
        g_xb[(size_t)row * D + c] = __float2bfloat16(v);
        s += v;
        ss += v * v;
    }
    #pragma unroll
    for (int o = 16; o > 0; o >>= 1) {
        s  += __shfl_down_sync(0xffffffffu, s,  o);
        ss += __shfl_down_sync(0xffffffffu, ss, o);
    }
    __shared__ float sh_s[8], sh_ss[8];
    int w = t >> 5, l = t & 31;
    if (l == 0) { sh_s[w] = s; sh_ss[w] = ss; }
    __syncthreads();
    if (t == 0) {
        float S = 0.f, SS = 0.f;
        int nw = blockDim.x >> 5;
        for (int i = 0; i < nw; i++) { S += sh_s[i]; SS += sh_ss[i]; }
        const float EPS = 1e-6f;
        g_u[row] = SS + 2.0f * EPS * S + (float)D * EPS * EPS;
        g_v[row] = SS - 2.0f * EPS * S;
    }
}

__device__ __forceinline__ uint32_t smem_u32(const void* p) {
    return (uint32_t)__cvta_generic_to_shared(p);
}

// Pairwise tile kernel. CTA = 128x128 tile, 8 warps 2x4, warp tile 64x32,
// mma m16n8k16 bf16, ldmatrix, 2-stage cp.async.cg double buffer, 2 CTA/SM.
// DIAG=true handles the 64 diagonal tiles (needs j>i mask); DIAG=false the rest.
template<bool DIAG>
__global__ __launch_bounds__(256, 2) void pair_kernel(float* __restrict__ out,
                                                      int B, int D, int NT,
                                                      double inv, int total) {
    extern __shared__ __align__(16) __nv_bfloat16 dyn[];
    __shared__ float red[8];

    int ti, tj;
    if (DIAG) {
        ti = tj = blockIdx.x;
    } else {
        int p = blockIdx.x;
        ti = 0;
        while (p >= NT - 1 - ti) { p -= NT - 1 - ti; ti++; }
        tj = ti + 1 + p;
    }

    const int tid  = threadIdx.x;
    const int warp = tid >> 5;
    const int lane = tid & 31;
    const int grp  = lane >> 2;
    const int tg   = lane & 3;
    const int wm   = warp >> 2;   // 0..1
    const int wn   = warp & 3;    // 0..3

    float acc[4][4][4];
    #pragma unroll
    for (int a = 0; a < 4; a++)
        #pragma unroll
        for (int b = 0; b < 4; b++)
            #pragma unroll
            for (int c = 0; c < 4; c++) acc[a][b][c] = 0.f;

    const int r0 = ti * TILE;
    const int c0 = tj * TILE;

    const uint32_t dynBase = smem_u32(dyn);

    // ldmatrix base offsets (within a stage)
    const int rowA = wm * 64 + (lane & 15);
    const int aSel = (lane >> 4) * 8;
    const uint32_t aOff = (uint32_t)(rowA * LDSA + aSel) * 2u;
    const int colB = wn * 32 + ((lane >> 4) << 3) + (lane & 7);
    const int bSel = ((lane >> 3) & 1) * 8;
    const uint32_t bOff = (uint32_t)(TILE * LDSA + colB * LDSA + bSel) * 2u;

    const int sRow = tid >> 3;
    const int sC8  = tid & 7;
    const uint32_t stOff = (uint32_t)(sRow * LDSA + sC8 * 8) * 2u;

    const int NC = D / KC;   // 4 for D=256

    // prologue: stage chunk 0 into stage buffer 0
    {
        #pragma unroll
        for (int it = 0; it < 4; it++) {
            int row = sRow + 32 * it;
            uint32_t sa = dynBase + stOff + (uint32_t)(32 * it * LDSA) * 2u;
            uint32_t sb = sa + (uint32_t)(TILE * LDSA) * 2u;
            const void* ga = &g_xb[(size_t)(r0 + row) * D + sC8 * 8];
            const void* gb = &g_xb[(size_t)(c0 + row) * D + sC8 * 8];
            asm volatile("cp.async.cg.shared.global [%0], [%1], 16;\n" :: "r"(sa), "l"(ga));
            asm volatile("cp.async.cg.shared.global [%0], [%1], 16;\n" :: "r"(sb), "l"(gb));
        }
        asm volatile("cp.async.commit_group;\n");
    }

    for (int c = 0; c < NC; c++) {
        if (c + 1 < NC) {
            // prefetch chunk c+1 into the other stage buffer
            uint32_t base = dynBase + (uint32_t)((c + 1) & 1) * STAGE_BYTES;
            int kc = (c + 1) * KC;
            #pragma unroll
            for (int it = 0; it < 4; it++) {
                int row = sRow + 32 * it;
                uint32_t sa = base + stOff + (uint32_t)(32 * it * LDSA) * 2u;
                uint32_t sb = sa + (uint32_t)(TILE * LDSA) * 2u;
                const void* ga = &g_xb[(size_t)(r0 + row) * D + kc + sC8 * 8];
                const void* gb = &g_xb[(size_t)(c0 + row) * D + kc + sC8 * 8];
                asm volatile("cp.async.cg.shared.global [%0], [%1], 16;\n" :: "r"(sa), "l"(ga));
                asm volatile("cp.async.cg.shared.global [%0], [%1], 16;\n" :: "r"(sb), "l"(gb));
            }
            asm volatile("cp.async.commit_group;\n");
            asm volatile("cp.async.wait_group 1;\n");   // chunk c arrived
        } else {
            asm volatile("cp.async.wait_group 0;\n");
        }
        __syncthreads();

        const uint32_t sBase = dynBase + (uint32_t)(c & 1) * STAGE_BYTES;
        #pragma unroll
        for (int ks = 0; ks < KC / 16; ks++) {
            uint32_t af[4][4];
            #pragma unroll
            for (int mt = 0; mt < 4; mt++) {
                uint32_t addr = sBase + aOff + (uint32_t)(mt * 16 * LDSA) * 2u + (uint32_t)ks * 32u;
                asm volatile("ldmatrix.sync.aligned.m8n8.x4.shared.b16 {%0,%1,%2,%3}, [%4];\n"
                             : "=r"(af[mt][0]), "=r"(af[mt][1]), "=r"(af[mt][2]), "=r"(af[mt][3])
                             : "r"(addr));
            }
            uint32_t bf[4][2];
            #pragma unroll
            for (int np = 0; np < 2; np++) {
                uint32_t addr = sBase + bOff + (uint32_t)(np * 16 * LDSA) * 2u + (uint32_t)ks * 32u;
                asm volatile("ldmatrix.sync.aligned.m8n8.x4.shared.b16 {%0,%1,%2,%3}, [%4];\n"
                             : "=r"(bf[2 * np][0]), "=r"(bf[2 * np][1]),
                               "=r"(bf[2 * np + 1][0]), "=r"(bf[2 * np + 1][1])
                             : "r"(addr));
            }
            #pragma unroll
            for (int mt = 0; mt < 4; mt++)
                #pragma unroll
                for (int nt = 0; nt < 4; nt++) {
                    float* d = acc[mt][nt];
                    asm volatile(
                        "mma.sync.aligned.m16n8k16.row.col.f32.bf16.bf16.f32 "
                        "{%0,%1,%2,%3}, {%4,%5,%6,%7}, {%8,%9}, {%0,%1,%2,%3};\n"
                        : "+f"(d[0]), "+f"(d[1]), "+f"(d[2]), "+f"(d[3])
                        : "r"(af[mt][0]), "r"(af[mt][1]), "r"(af[mt][2]), "r"(af[mt][3]),
                          "r"(bf[nt][0]), "r"(bf[nt][1]));
                }
        }
        __syncthreads();   // buffer (c&1) free for reuse at chunk c+2
    }

    // Epilogue
    int iRow[8]; float uI[8]; int lbI[8];
    #pragma unroll
    for (int mt = 0; mt < 4; mt++) {
        int i0 = r0 + wm * 64 + mt * 16 + grp;
        iRow[mt * 2]     = i0;
        iRow[mt * 2 + 1] = i0 + 8;
    }
    #pragma unroll
    for (int u = 0; u < 8; u++) { uI[u] = g_u[iRow[u]]; lbI[u] = g_lab[iRow[u]]; }

    int jCol[8]; float vJ[8]; int lbJ[8];
    #pragma unroll
    for (int nt = 0; nt < 4; nt++) {
        int j0 = c0 + wn * 32 + nt * 8 + tg * 2;
        jCol[nt * 2]     = j0;
        jCol[nt * 2 + 1] = j0 + 1;
    }
    #pragma unroll
    for (int u = 0; u < 8; u++) { vJ[u] = g_v[jCol[u]]; lbJ[u] = g_lab[jCol[u]]; }

    float tsum = 0.f;
    #pragma unroll
    for (int mt = 0; mt < 4; mt++)
        #pragma unroll
        for (int nt = 0; nt < 4; nt++)
            #pragma unroll
            for (int h = 0; h < 4; h++) {
                int ui = mt * 2 + (h >> 1);
                int uj = nt * 2 + (h & 1);
                float gv = acc[mt][nt][h];
                float sq = fmaf(gv, -2.0f, uI[ui] + vJ[uj]);
                bool same = (lbI[ui] == lbJ[uj]);
                float val = same ? sq : 0.0f;        // common path (sq >= 1)
                if (sq < 1.0f) {                     // ~never taken
                    if (same) {
                        val = fmaxf(sq, 1e-12f);
                    } else {
                        float dd = sqrtf(fmaxf(sq, 1e-12f));
                        float tt = 1.0f - dd;
                        val = tt * tt;
                    }
                }
                if (DIAG) {
                    if (jCol[uj] > iRow[ui]) tsum += val;
                } else {
                    tsum += val;
                }
            }

    #pragma unroll
    for (int o = 16; o > 0; o >>= 1)
        tsum += __shfl_down_sync(0xffffffffu, tsum, o);
    if (lane == 0) red[warp] = tsum;
    __syncthreads();
    if (tid == 0) {
        float s = 0.f;
        #pragma unroll
        for (int i = 0; i < 8; i++) s += red[i];
        atomicAdd(&g_acc, (double)s);
        __threadfence();
        int t = atomicAdd(&g_done, 1);
        if (t == total - 1) {
            g_done = 0;
            double v = atomicAdd(&g_acc, 0.0);
            out[0] = (float)(v * inv);
        }
    }
}

extern "C" void kernel_launch(void* const* d_in, const int* in_sizes, int n_in,
                              void* d_out, int out_size) {
    const float* x     = (const float*)d_in[0];
    const int*   lab32 = (const int*)d_in[1];
    int B = in_sizes[1];
    int D = in_sizes[0] / B;
    int NT = B / TILE;
    int offdiag = NT * (NT - 1) / 2;
    int total = offdiag + NT;
    double cnt = (double)B * (B - 1) / 2.0;
    double inv = 1.0 / (cnt + 1e-6);

    cudaFuncSetAttribute(pair_kernel<false>,
                         cudaFuncAttributeMaxDynamicSharedMemorySize, SMEM_DYN);
    cudaFuncSetAttribute(pair_kernel<true>,
                         cudaFuncAttributeMaxDynamicSharedMemorySize, SMEM_DYN);

    prep_kernel<<<B + 1, 256>>>(x, lab32, B, D);
    pair_kernel<false><<<offdiag, 256, SMEM_DYN>>>((float*)d_out, B, D, NT, inv, total);
    pair_kernel<true><<<NT, 256, SMEM_DYN>>>((float*)d_out, B, D, NT, inv, total);
}

// round 5
// speedup vs baseline: 2.1842x; 1.1081x over previous
#include <cuda_runtime.h>
#include <cuda_bf16.h>
#include <cstdint>

#define BMAX 8192
#define DMAX 256

#define TILE 128
#define KC   64
#define LDSA 72   // smem row stride (bf16 elems); 144B pitch, conflict-free LDSM

#define STAGE_BYTES (2u * TILE * LDSA * 2u)     // A+B tiles per stage
#define SMEM_DYN    (2u * STAGE_BYTES)          // 2 stages = 73728 B

// Scratch (allocation-free rule: __device__ globals)
__device__ __align__(16) __nv_bfloat16 g_xb[BMAX * DMAX];
__device__ float  g_u[BMAX];     // sqn + 2eps*rs + D*eps^2
__device__ float  g_v[BMAX];     // sqn - 2eps*rs
__device__ int    g_lab[BMAX];
__device__ double g_acc;
__device__ int    g_done;        // zero-init; reset by finalizing CTA each replay

// prep v2: warp-per-row, float4 loads, one shfl reduction.
// Block 0 additionally: label dtype detect (int64 -> all odd int32 words zero),
// label normalize, acc zero.
__global__ __launch_bounds__(256) void prep_kernel(const float* __restrict__ x,
                                                   const int* __restrict__ lab32,
                                                   int B, int D) {
    const int t = threadIdx.x;

    if (blockIdx.x == 0) {
        __shared__ int s_any;
        if (t == 0) { s_any = 0; g_acc = 0.0; }
        __syncthreads();
        int any = 0;
        for (int idx = 1 + 2 * t; idx < B; idx += 2 * blockDim.x)
            any |= lab32[idx];
        if (any) atomicOr(&s_any, 1);
        __syncthreads();
        int is32 = (s_any != 0);
        for (int r = t; r < B; r += blockDim.x)
            g_lab[r] = is32 ? lab32[r] : lab32[2 * r];
        // fall through to row work
    }

    const int warp = t >> 5;
    const int lane = t & 31;
    const int warpsPerBlock = blockDim.x >> 5;
    const int nWarps = gridDim.x * warpsPerBlock;
    const float EPS = 1e-6f;

    for (int row = blockIdx.x * warpsPerBlock + warp; row < B; row += nWarps) {
        const float* xr = x + (size_t)row * D;
        float s = 0.f, ss = 0.f;
        // lane owns 8 contiguous floats per 256-wide slice
        for (int c0 = lane * 8; c0 < D; c0 += 256) {
            float4 v0 = *reinterpret_cast<const float4*>(xr + c0);
            float4 v1 = *reinterpret_cast<const float4*>(xr + c0 + 4);
            s  += v0.x + v0.y + v0.z + v0.w + v1.x + v1.y + v1.z + v1.w;
            ss += v0.x * v0.x + v0.y * v0.y + v0.z * v0.z + v0.w * v0.w
                + v1.x * v1.x + v1.y * v1.y + v1.z * v1.z + v1.w * v1.w;
            // convert to bf16, pack 8 -> uint4 (16B store)
            __nv_bfloat162 p0 = __floats2bfloat162_rn(v0.x, v0.y);
            __nv_bfloat162 p1 = __floats2bfloat162_rn(v0.z, v0.w);
            __nv_bfloat162 p2 = __floats2bfloat162_rn(v1.x, v1.y);
            __nv_bfloat162 p3 = __floats2bfloat162_rn(v1.z, v1.w);
            uint4 pk;
            pk.x = *reinterpret_cast<uint32_t*>(&p0);
            pk.y = *reinterpret_cast<uint32_t*>(&p1);
            pk.z = *reinterpret_cast<uint32_t*>(&p2);
            pk.w = *reinterpret_cast<uint32_t*>(&p3);
            *reinterpret_cast<uint4*>(&g_xb[(size_t)row * D + c0]) = pk;
        }
        #pragma unroll
        for (int o = 16; o > 0; o >>= 1) {
            s  += __shfl_down_sync(0xffffffffu, s,  o);
            ss += __shfl_down_sync(0xffffffffu, ss, o);
        }
        if (lane == 0) {
            g_u[row] = ss + 2.0f * EPS * s + (float)D * EPS * EPS;
            g_v[row] = ss - 2.0f * EPS * s;
        }
    }
}

__device__ __forceinline__ uint32_t smem_u32(const void* p) {
    return (uint32_t)__cvta_generic_to_shared(p);
}

// Merged pairwise tile kernel (off-diag tiles first, then diagonal tiles).
// CTA = 128x128 tile, 8 warps 2x4, warp tile 64x32, mma m16n8k16 bf16,
// ldmatrix, 2-stage cp.async.cg double buffer, 2 CTA/SM. Fused finalize.
__global__ __launch_bounds__(256, 2) void pair_kernel(float* __restrict__ out,
                                                      int B, int D, int NT,
                                                      int offdiag, double inv) {
    extern __shared__ __align__(16) __nv_bfloat16 dyn[];
    __shared__ float red[8];

    int ti, tj;
    bool isDiag;
    {
        int p = blockIdx.x;
        if (p < offdiag) {
            ti = 0;
            while (p >= NT - 1 - ti) { p -= NT - 1 - ti; ti++; }
            tj = ti + 1 + p;
            isDiag = false;
        } else {
            ti = tj = p - offdiag;
            isDiag = true;
        }
    }

    const int tid  = threadIdx.x;
    const int warp = tid >> 5;
    const int lane = tid & 31;
    const int grp  = lane >> 2;
    const int tg   = lane & 3;
    const int wm   = warp >> 2;   // 0..1
    const int wn   = warp & 3;    // 0..3

    float acc[4][4][4];
    #pragma unroll
    for (int a = 0; a < 4; a++)
        #pragma unroll
        for (int b = 0; b < 4; b++)
            #pragma unroll
            for (int c = 0; c < 4; c++) acc[a][b][c] = 0.f;

    const int r0 = ti * TILE;
    const int c0 = tj * TILE;

    const uint32_t dynBase = smem_u32(dyn);

    // ldmatrix base offsets (within a stage)
    const int rowA = wm * 64 + (lane & 15);
    const int aSel = (lane >> 4) * 8;
    const uint32_t aOff = (uint32_t)(rowA * LDSA + aSel) * 2u;
    const int colB = wn * 32 + ((lane >> 4) << 3) + (lane & 7);
    const int bSel = ((lane >> 3) & 1) * 8;
    const uint32_t bOff = (uint32_t)(TILE * LDSA + colB * LDSA + bSel) * 2u;

    const int sRow = tid >> 3;
    const int sC8  = tid & 7;
    const uint32_t stOff = (uint32_t)(sRow * LDSA + sC8 * 8) * 2u;

    const int NC = D / KC;   // 4 for D=256

    // prologue: stage chunk 0 into stage buffer 0
    {
        #pragma unroll
        for (int it = 0; it < 4; it++) {
            int row = sRow + 32 * it;
            uint32_t sa = dynBase + stOff + (uint32_t)(32 * it * LDSA) * 2u;
            uint32_t sb = sa + (uint32_t)(TILE * LDSA) * 2u;
            const void* ga = &g_xb[(size_t)(r0 + row) * D + sC8 * 8];
            const void* gb = &g_xb[(size_t)(c0 + row) * D + sC8 * 8];
            asm volatile("cp.async.cg.shared.global [%0], [%1], 16;\n" :: "r"(sa), "l"(ga));
            asm volatile("cp.async.cg.shared.global [%0], [%1], 16;\n" :: "r"(sb), "l"(gb));
        }
        asm volatile("cp.async.commit_group;\n");
    }

    for (int c = 0; c < NC; c++) {
        if (c + 1 < NC) {
            uint32_t base = dynBase + (uint32_t)((c + 1) & 1) * STAGE_BYTES;
            int kc = (c + 1) * KC;
            #pragma unroll
            for (int it = 0; it < 4; it++) {
                int row = sRow + 32 * it;
                uint32_t sa = base + stOff + (uint32_t)(32 * it * LDSA) * 2u;
                uint32_t sb = sa + (uint32_t)(TILE * LDSA) * 2u;
                const void* ga = &g_xb[(size_t)(r0 + row) * D + kc + sC8 * 8];
                const void* gb = &g_xb[(size_t)(c0 + row) * D + kc + sC8 * 8];
                asm volatile("cp.async.cg.shared.global [%0], [%1], 16;\n" :: "r"(sa), "l"(ga));
                asm volatile("cp.async.cg.shared.global [%0], [%1], 16;\n" :: "r"(sb), "l"(gb));
            }
            asm volatile("cp.async.commit_group;\n");
            asm volatile("cp.async.wait_group 1;\n");   // chunk c arrived
        } else {
            asm volatile("cp.async.wait_group 0;\n");
        }
        __syncthreads();

        const uint32_t sBase = dynBase + (uint32_t)(c & 1) * STAGE_BYTES;
        #pragma unroll
        for (int ks = 0; ks < KC / 16; ks++) {
            uint32_t af[4][4];
            #pragma unroll
            for (int mt = 0; mt < 4; mt++) {
                uint32_t addr = sBase + aOff + (uint32_t)(mt * 16 * LDSA) * 2u + (uint32_t)ks * 32u;
                asm volatile("ldmatrix.sync.aligned.m8n8.x4.shared.b16 {%0,%1,%2,%3}, [%4];\n"
                             : "=r"(af[mt][0]), "=r"(af[mt][1]), "=r"(af[mt][2]), "=r"(af[mt][3])
                             : "r"(addr));
            }
            uint32_t bf[4][2];
            #pragma unroll
            for (int np = 0; np < 2; np++) {
                uint32_t addr = sBase + bOff + (uint32_t)(np * 16 * LDSA) * 2u + (uint32_t)ks * 32u;
                asm volatile("ldmatrix.sync.aligned.m8n8.x4.shared.b16 {%0,%1,%2,%3}, [%4];\n"
                             : "=r"(bf[2 * np][0]), "=r"(bf[2 * np][1]),
                               "=r"(bf[2 * np + 1][0]), "=r"(bf[2 * np + 1][1])
                             : "r"(addr));
            }
            #pragma unroll
            for (int mt = 0; mt < 4; mt++)
                #pragma unroll
                for (int nt = 0; nt < 4; nt++) {
                    float* d = acc[mt][nt];
                    asm volatile(
                        "mma.sync.aligned.m16n8k16.row.col.f32.bf16.bf16.f32 "
                        "{%0,%1,%2,%3}, {%4,%5,%6,%7}, {%8,%9}, {%0,%1,%2,%3};\n"
                        : "+f"(d[0]), "+f"(d[1]), "+f"(d[2]), "+f"(d[3])
                        : "r"(af[mt][0]), "r"(af[mt][1]), "r"(af[mt][2]), "r"(af[mt][3]),
                          "r"(bf[nt][0]), "r"(bf[nt][1]));
                }
        }
        __syncthreads();   // buffer (c&1) free for reuse at chunk c+2
    }

    // Epilogue
    int iRow[8]; float uI[8]; int lbI[8];
    #pragma unroll
    for (int mt = 0; mt < 4; mt++) {
        int i0 = r0 + wm * 64 + mt * 16 + grp;
        iRow[mt * 2]     = i0;
        iRow[mt * 2 + 1] = i0 + 8;
    }
    #pragma unroll
    for (int u = 0; u < 8; u++) { uI[u] = g_u[iRow[u]]; lbI[u] = g_lab[iRow[u]]; }

    int jCol[8]; float vJ[8]; int lbJ[8];
    #pragma unroll
    for (int nt = 0; nt < 4; nt++) {
        int j0 = c0 + wn * 32 + nt * 8 + tg * 2;
        jCol[nt * 2]     = j0;
        jCol[nt * 2 + 1] = j0 + 1;
    }
    #pragma unroll
    for (int u = 0; u < 8; u++) { vJ[u] = g_v[jCol[u]]; lbJ[u] = g_lab[jCol[u]]; }

    float tsum = 0.f;
    #pragma unroll
    for (int mt = 0; mt < 4; mt++)
        #pragma unroll
        for (int nt = 0; nt < 4; nt++)
            #pragma unroll
            for (int h = 0; h < 4; h++) {
                int ui = mt * 2 + (h >> 1);
                int uj = nt * 2 + (h & 1);
                float gv = acc[mt][nt][h];
                float sq = fmaf(gv, -2.0f, uI[ui] + vJ[uj]);
                bool same = (lbI[ui] == lbJ[uj]);
                float val = same ? sq : 0.0f;        // common path (sq >= 1)
                if (sq < 1.0f) {                     // ~never taken
                    if (same) {
                        val = fmaxf(sq, 1e-12f);
                    } else {
                        float dd = sqrtf(fmaxf(sq, 1e-12f));
                        float tt = 1.0f - dd;
                        val = tt * tt;
                    }
                }
                if (!isDiag || jCol[uj] > iRow[ui]) tsum += val;
            }

    #pragma unroll
    for (int o = 16; o > 0; o >>= 1)
        tsum += __shfl_down_sync(0xffffffffu, tsum, o);
    if (lane == 0) red[warp] = tsum;
    __syncthreads();
    if (tid == 0) {
        float s = 0.f;
        #pragma unroll
        for (int i = 0; i < 8; i++) s += red[i];
        atomicAdd(&g_acc, (double)s);
        __threadfence();
        int t = atomicAdd(&g_done, 1);
        if (t == (int)gridDim.x - 1) {
            g_done = 0;
            double v = atomicAdd(&g_acc, 0.0);
            out[0] = (float)(v * inv);
        }
    }
}

extern "C" void kernel_launch(void* const* d_in, const int* in_sizes, int n_in,
                              void* d_out, int out_size) {
    const float* x     = (const float*)d_in[0];
    const int*   lab32 = (const int*)d_in[1];
    int B = in_sizes[1];
    int D = in_sizes[0] / B;
    int NT = B / TILE;
    int offdiag = NT * (NT - 1) / 2;
    int total = offdiag + NT;
    double cnt = (double)B * (B - 1) / 2.0;
    double inv = 1.0 / (cnt + 1e-6);

    cudaFuncSetAttribute(pair_kernel,
                         cudaFuncAttributeMaxDynamicSharedMemorySize, SMEM_DYN);

    prep_kernel<<<256, 256>>>(x, lab32, B, D);
    pair_kernel<<<total, 256, SMEM_DYN>>>((float*)d_out, B, D, NT, offdiag, inv);
}

// round 7
// speedup vs baseline: 2.7980x; 1.2810x over previous
#include <cuda_runtime.h>
#include <cuda_bf16.h>
#include <cstdint>

#define BMAX 8192
#define DMAX 256
#define TILE 128
#define LDS32 40     // smem row stride in bf16 elems (80B pitch; conflict-free ldmatrix)

// Scratch (allocation-free rule: __device__ globals)
__device__ __align__(16) __nv_bfloat16 g_x32[BMAX * 32];  // first 32 coords, bf16
__device__ float  g_rs[BMAX];     // row sum (exact fp32)
__device__ float  g_sqn[BMAX];    // row squared norm
__device__ float  g_n32[BMAX];    // squared norm of first 32 coords
__device__ int    g_lab[BMAX];
__device__ double g_S[512];       // [2][256] per-class vector sums
__device__ double g_qsum[2];      // per-class sum of squared norms
__device__ double g_acc;
__device__ int    g_done;

// ---------------- init: label dtype detect + normalize, zero accumulators ----
__global__ void init_kernel(const int* __restrict__ lab32, int B) {
    const int t = threadIdx.x;
    __shared__ int s_any;
    if (t == 0) { s_any = 0; g_acc = 0.0; g_qsum[0] = 0.0; g_qsum[1] = 0.0; }
    for (int i = t; i < 512; i += blockDim.x) g_S[i] = 0.0;
    __syncthreads();
    int any = 0;
    for (int idx = 1 + 2 * t; idx < B; idx += 2 * blockDim.x)
        any |= lab32[idx];
    if (any) atomicOr(&s_any, 1);
    __syncthreads();
    const int is32 = (s_any != 0);
    for (int r = t; r < B; r += blockDim.x)
        g_lab[r] = is32 ? lab32[r] : lab32[2 * r];
}

// ---------------- prep: per-row stats, bf16 x32, per-class reductions --------
// Warp-per-row; assumes D == 256 (dataset). Lane owns dims [lane*8, lane*8+8).
__global__ __launch_bounds__(256) void prep_kernel(const float* __restrict__ x,
                                                   int B, int D) {
    const int t = threadIdx.x, warp = t >> 5, lane = t & 31;
    const int wpb = 8;                       // warps per block
    const int nW = gridDim.x * wpb;
    __shared__ float sS[2][256];
    __shared__ double sQ[2];
    for (int i = t; i < 512; i += 256) ((float*)sS)[i] = 0.f;
    if (t < 2) sQ[t] = 0.0;
    __syncthreads();
    const int lab0 = g_lab[0];

    float sc0[8] = {0,0,0,0,0,0,0,0};
    float sc1[8] = {0,0,0,0,0,0,0,0};

    for (int row = blockIdx.x * wpb + warp; row < B; row += nW) {
        const float* xr = x + (size_t)row * D;
        const int c0 = lane * 8;
        float4 v0 = *reinterpret_cast<const float4*>(xr + c0);
        float4 v1 = *reinterpret_cast<const float4*>(xr + c0 + 4);
        float v[8] = {v0.x, v0.y, v0.z, v0.w, v1.x, v1.y, v1.z, v1.w};
        float s = 0.f, ss = 0.f;
        #pragma unroll
        for (int k = 0; k < 8; k++) { s += v[k]; ss += v[k] * v[k]; }
        float ss32 = (lane < 4) ? ss : 0.f;

        const int cls = (g_lab[row] == lab0) ? 0 : 1;
        if (cls == 0) {
            #pragma unroll
            for (int k = 0; k < 8; k++) sc0[k] += v[k];
        } else {
            #pragma unroll
            for (int k = 0; k < 8; k++) sc1[k] += v[k];
        }

        if (lane < 4) {   // store bf16 of first 32 coords
            __nv_bfloat162 p0 = __floats2bfloat162_rn(v[0], v[1]);
            __nv_bfloat162 p1 = __floats2bfloat162_rn(v[2], v[3]);
            __nv_bfloat162 p2 = __floats2bfloat162_rn(v[4], v[5]);
            __nv_bfloat162 p3 = __floats2bfloat162_rn(v[6], v[7]);
            uint4 pk;
            pk.x = *reinterpret_cast<uint32_t*>(&p0);
            pk.y = *reinterpret_cast<uint32_t*>(&p1);
            pk.z = *reinterpret_cast<uint32_t*>(&p2);
            pk.w = *reinterpret_cast<uint32_t*>(&p3);
            *reinterpret_cast<uint4*>(&g_x32[(size_t)row * 32 + lane * 8]) = pk;
        }

        #pragma unroll
        for (int o = 16; o > 0; o >>= 1) {
            s    += __shfl_down_sync(0xffffffffu, s,    o);
            ss   += __shfl_down_sync(0xffffffffu, ss,   o);
            ss32 += __shfl_down_sync(0xffffffffu, ss32, o);
        }
        if (lane == 0) {
            g_rs[row]  = s;
            g_sqn[row] = ss;
            g_n32[row] = ss32;
            atomicAdd(&sQ[cls], (double)ss);
        }
    }

    // per-class vector sums: registers -> shared -> global double
    #pragma unroll
    for (int k = 0; k < 8; k++) {
        atomicAdd(&sS[0][lane * 8 + k], sc0[k]);
        atomicAdd(&sS[1][lane * 8 + k], sc1[k]);
    }
    __syncthreads();
    for (int i = t; i < 512; i += 256)
        atomicAdd(&g_S[i], (double)((float*)sS)[i]);
    if (t < 2) atomicAdd(&g_qsum[t], sQ[t]);
}

// ---------------- closed-form same-pair sum (one block, 1024 threads) --------
__global__ void closed_kernel(int B, int D) {
    const int t = threadIdx.x;
    __shared__ int sscan[1024];
    __shared__ double sw[32];
    const int lab0 = g_lab[0];
    const int per = B / 1024;     // 8

    int cls[8];
    int cnt = 0;
    const int base = t * per;
    #pragma unroll
    for (int k = 0; k < 8; k++) {
        cls[k] = (g_lab[base + k] == lab0) ? 0 : 1;
        cnt += cls[k];
    }
    sscan[t] = cnt;
    __syncthreads();
    for (int o = 1; o < 1024; o <<= 1) {
        int v = (t >= o) ? sscan[t - o] : 0;
        __syncthreads();
        sscan[t] += v;
        __syncthreads();
    }
    const int n1 = sscan[1023];
    const int n0 = B - n1;

    int run1 = sscan[t] - cnt;    // exclusive class-1 prefix for this segment
    double R = 0.0;
    #pragma unroll
    for (int k = 0; k < 8; k++) {
        int i = base + k;
        int c = cls[k];
        int rank = c ? run1 : (i - run1);
        run1 += c;
        int nc = c ? n1 : n0;
        R += (double)g_rs[i] * (double)(nc - 1 - 2 * rank);
    }
    double s2 = 0.0;
    if (t < 512) { double v = g_S[t]; s2 = v * v; }

    // reduce R and s2 across block
    const int lane = t & 31, warp = t >> 5;
    #pragma unroll
    for (int o = 16; o > 0; o >>= 1) {
        R  += __shfl_down_sync(0xffffffffu, R,  o);
        s2 += __shfl_down_sync(0xffffffffu, s2, o);
    }
    if (lane == 0) sw[warp] = R;
    __syncthreads();
    double Rtot = 0.0;
    if (t == 0) { for (int i = 0; i < 32; i++) Rtot += sw[i]; }
    __syncthreads();
    if (lane == 0) sw[warp] = s2;
    __syncthreads();
    if (t == 0) {
        double S2 = 0.0;
        for (int i = 0; i < 32; i++) S2 += sw[i];
        const double EPS = 1e-6;
        double q0 = g_qsum[0], q1 = g_qsum[1];
        double npairs = 0.5 * ((double)n0 * (n0 - 1) + (double)n1 * (n1 - 1));
        double res = (double)n0 * q0 + (double)n1 * q1 - S2
                   + 2.0 * EPS * Rtot + (double)D * EPS * EPS * npairs;
        atomicAdd(&g_acc, res);
    }
}

// ---------------- exact correction for screened pairs (cold path) ------------
__device__ __noinline__ void correction(const float* __restrict__ x,
                                        int i, int j, int D) {
    double dot = 0.0;
    for (int d = 0; d < D; d++)
        dot += (double)x[(size_t)i * D + d] * (double)x[(size_t)j * D + d];
    const float EPS = 1e-6f;
    float sq = (float)((double)g_sqn[i] + (double)g_sqn[j] - 2.0 * dot)
             + 2.0f * EPS * (g_rs[i] - g_rs[j]) + (float)D * EPS * EPS;
    bool same = (g_lab[i] == g_lab[j]);
    float assumed = same ? sq : 0.0f;
    float truev;
    if (same) {
        truev = fmaxf(sq, 1e-12f);
    } else {
        float dd = sqrtf(fmaxf(sq, 1e-12f));
        float tt = fmaxf(1.0f - dd, 0.0f);
        truev = tt * tt;
    }
    atomicAdd(&g_acc, (double)(truev - assumed));
}

__device__ __forceinline__ uint32_t smem_u32(const void* p) {
    return (uint32_t)__cvta_generic_to_shared(p);
}

// ---------------- screen: 32-dim pairwise lower bound + finalize -------------
// CTA = 128x128 tile on first-32-coords Gram, 8 warps 2x4, warp tile 64x32.
__global__ __launch_bounds__(256, 2) void screen_kernel(const float* __restrict__ x,
                                                        float* __restrict__ out,
                                                        int B, int D, int NT,
                                                        int offdiag, double inv) {
    __shared__ __nv_bfloat16 sA[TILE * LDS32];
    __shared__ __nv_bfloat16 sBt[TILE * LDS32];
    __shared__ float sNI[TILE], sNJ[TILE];

    int ti, tj;
    bool isDiag;
    {
        int p = blockIdx.x;
        if (p < offdiag) {
            ti = 0;
            while (p >= NT - 1 - ti) { p -= NT - 1 - ti; ti++; }
            tj = ti + 1 + p;
            isDiag = false;
        } else {
            ti = tj = p - offdiag;
            isDiag = true;
        }
    }
    const int r0 = ti * TILE;
    const int c0 = tj * TILE;

    const int tid  = threadIdx.x;
    const int warp = tid >> 5;
    const int lane = tid & 31;
    const int grp  = lane >> 2;
    const int tg   = lane & 3;
    const int wm   = warp >> 2;
    const int wn   = warp & 3;

    if (tid < TILE) sNI[tid] = g_n32[r0 + tid];
    else            sNJ[tid - TILE] = g_n32[c0 + tid - TILE];

    // stage A/B tiles (128 rows x 32 bf16, stride LDS32)
    #pragma unroll
    for (int it = 0; it < 2; it++) {
        int idx = tid + 256 * it;
        int row = idx >> 2;
        int q   = idx & 3;
        *reinterpret_cast<uint4*>(&sA[row * LDS32 + q * 8]) =
            *reinterpret_cast<const uint4*>(&g_x32[(size_t)(r0 + row) * 32 + q * 8]);
        *reinterpret_cast<uint4*>(&sBt[row * LDS32 + q * 8]) =
            *reinterpret_cast<const uint4*>(&g_x32[(size_t)(c0 + row) * 32 + q * 8]);
    }
    __syncthreads();

    float acc[4][4][4];
    #pragma unroll
    for (int a = 0; a < 4; a++)
        #pragma unroll
        for (int b = 0; b < 4; b++)
            #pragma unroll
            for (int c = 0; c < 4; c++) acc[a][b][c] = 0.f;

    const int rowA = wm * 64 + (lane & 15);
    const int aSel = (lane >> 4) * 8;
    const uint32_t aBase = smem_u32(sA) + (uint32_t)(rowA * LDS32 + aSel) * 2u;
    const int colB = wn * 32 + ((lane >> 4) << 3) + (lane & 7);
    const int bSel = ((lane >> 3) & 1) * 8;
    const uint32_t bBase = smem_u32(sBt) + (uint32_t)(colB * LDS32 + bSel) * 2u;

    #pragma unroll
    for (int ks = 0; ks < 2; ks++) {
        uint32_t af[4][4];
        #pragma unroll
        for (int mt = 0; mt < 4; mt++) {
            uint32_t addr = aBase + (uint32_t)(mt * 16 * LDS32) * 2u + (uint32_t)ks * 32u;
            asm volatile("ldmatrix.sync.aligned.m8n8.x4.shared.b16 {%0,%1,%2,%3}, [%4];\n"
                         : "=r"(af[mt][0]), "=r"(af[mt][1]), "=r"(af[mt][2]), "=r"(af[mt][3])
                         : "r"(addr));
        }
        uint32_t bfm[4][2];
        #pragma unroll
        for (int np = 0; np < 2; np++) {
            uint32_t addr = bBase + (uint32_t)(np * 16 * LDS32) * 2u + (uint32_t)ks * 32u;
            asm volatile("ldmatrix.sync.aligned.m8n8.x4.shared.b16 {%0,%1,%2,%3}, [%4];\n"
                         : "=r"(bfm[2 * np][0]), "=r"(bfm[2 * np][1]),
                           "=r"(bfm[2 * np + 1][0]), "=r"(bfm[2 * np + 1][1])
                         : "r"(addr));
        }
        #pragma unroll
        for (int mt = 0; mt < 4; mt++)
            #pragma unroll
            for (int nt = 0; nt < 4; nt++) {
                float* d = acc[mt][nt];
                asm volatile(
                    "mma.sync.aligned.m16n8k16.row.col.f32.bf16.bf16.f32 "
                    "{%0,%1,%2,%3}, {%4,%5,%6,%7}, {%8,%9}, {%0,%1,%2,%3};\n"
                    : "+f"(d[0]), "+f"(d[1]), "+f"(d[2]), "+f"(d[3])
                    : "r"(af[mt][0]), "r"(af[mt][1]), "r"(af[mt][2]), "r"(af[mt][3]),
                      "r"(bfm[nt][0]), "r"(bfm[nt][1]));
            }
    }

    // epilogue: screen only (no accumulation in common path)
    int iL[8], jL[8];
    #pragma unroll
    for (int mt = 0; mt < 4; mt++) {
        iL[mt * 2]     = wm * 64 + mt * 16 + grp;
        iL[mt * 2 + 1] = iL[mt * 2] + 8;
    }
    #pragma unroll
    for (int nt = 0; nt < 4; nt++) {
        jL[nt * 2]     = wn * 32 + nt * 8 + tg * 2;
        jL[nt * 2 + 1] = jL[nt * 2] + 1;
    }
    float nI[8], nJ[8];
    #pragma unroll
    for (int u = 0; u < 8; u++) { nI[u] = sNI[iL[u]]; nJ[u] = sNJ[jL[u]]; }

    #pragma unroll
    for (int mt = 0; mt < 4; mt++)
        #pragma unroll
        for (int nt = 0; nt < 4; nt++)
            #pragma unroll
            for (int h = 0; h < 4; h++) {
                int ui = mt * 2 + (h >> 1);
                int uj = nt * 2 + (h & 1);
                float g = acc[mt][nt][h];
                float sq32 = nI[ui] + nJ[uj] - 2.0f * g;
                if (sq32 < 4.0f) {              // conservative: bf16 err << 3
                    int i = r0 + iL[ui];
                    int j = c0 + jL[uj];
                    if (!isDiag || j > i) correction(x, i, j, D);
                }
            }

    __syncthreads();
    if (tid == 0) {
        __threadfence();
        int t = atomicAdd(&g_done, 1);
        if (t == (int)gridDim.x - 1) {
            g_done = 0;
            double v = atomicAdd(&g_acc, 0.0);
            out[0] = (float)(v * inv);
        }
    }
}

extern "C" void kernel_launch(void* const* d_in, const int* in_sizes, int n_in,
                              void* d_out, int out_size) {
    const float* x     = (const float*)d_in[0];
    const int*   lab32 = (const int*)d_in[1];
    int B = in_sizes[1];
    int D = in_sizes[0] / B;
    int NT = B / TILE;
    int offdiag = NT * (NT - 1) / 2;
    int total = offdiag + NT;
    double cnt = (double)B * (B - 1) / 2.0;
    double inv = 1.0 / (cnt + 1e-6);

    init_kernel<<<1, 1024>>>(lab32, B);
    prep_kernel<<<256, 256>>>(x, B, D);
    closed_kernel<<<1, 1024>>>(B, D);
    screen_kernel<<<total, 256>>>(x, (float*)d_out, B, D, NT, offdiag, inv);
}